// round 11
// baseline (speedup 1.0000x reference)
#include <cuda_runtime.h>
#include <cuda_fp16.h>
#include <cstdint>

// Problem dims
#define MDIM 8192   // B*S
#define NDIM 4096
#define KDIM 4096
#define K16  (KDIM / 16)      // 256

// GEMM tiling: 128x128 CTA, 8 warps (4m x 2n), warp tile 32x64
#define TM 128
#define TN 128
#define KC 64                 // k64 chunk = 4 k16 steps, 128B B rows
#define NK (KDIM / KC)        // 64
#define NSTAGE_B 5
#define B_TILE_BYTES (TN * KC * 2)          // 16384
#define SMEM_DYN (NSTAGE_B * B_TILE_BYTES)  // 81920

// Pre-pass grid split (256-thread blocks)
#define ACONV_BLOCKS ((MDIM / 16) * K16 / 8)        // 16384 (8 warps/blk)
#define DEQ_BLOCKS   (((KDIM / 8) * NDIM) / 256)    // 8192

// Scratch (allocation-free rule: __device__ globals)
// A fragments: per (m16, k16): 512B, lane l owns bytes [16l,16l+16) = a0..a3
__device__ uint4 g_Afrag[(MDIM / 16) * (size_t)K16 * 32 + 64];
// W fp16, [N, K] linear (K-major) for the cp.async->LDSM B path
__device__ uint4 g_W16[(NDIM * (size_t)KDIM) / 8];

// ---------------------------------------------------------------------------
__device__ __forceinline__ uint32_t smem_u32(const void* p) {
    uint32_t r;
    asm("{ .reg .u64 t; cvta.to.shared.u64 t, %1; cvt.u32.u64 %0, t; }"
        : "=r"(r) : "l"(p));
    return r;
}

__device__ __forceinline__ void cp_async16(uint32_t s, const void* g) {
    asm volatile("cp.async.cg.shared.global [%0], [%1], 16;"
                 :: "r"(s), "l"(__cvta_generic_to_global(g)) : "memory");
}

#define LDM_X4(r, addr)                                                        \
    asm volatile("ldmatrix.sync.aligned.m8n8.x4.shared.b16 {%0,%1,%2,%3}, [%4];" \
                 : "=r"((r)[0]), "=r"((r)[1]), "=r"((r)[2]), "=r"((r)[3])      \
                 : "r"(addr))

__device__ __forceinline__ void mma16816(float* d, const uint32_t* a,
                                         const uint32_t* b) {
    asm volatile(
        "mma.sync.aligned.m16n8k16.row.col.f32.f16.f16.f32 "
        "{%0,%1,%2,%3}, {%4,%5,%6,%7}, {%8,%9}, {%0,%1,%2,%3};"
        : "+f"(d[0]), "+f"(d[1]), "+f"(d[2]), "+f"(d[3])
        : "r"(a[0]), "r"(a[1]), "r"(a[2]), "r"(a[3]), "r"(b[0]), "r"(b[1]));
}

__device__ __forceinline__ uint32_t pack_h2(float x, float y) {
    __half2 h = __floats2half2_rn(x, y);
    return *(uint32_t*)&h;
}

// ---------------------------------------------------------------------------
// Merged pre-pass.
// Blocks [0, ACONV_BLOCKS): A fp32 -> fp16 fragments (warp per (m16,k16)).
// Blocks [ACONV_BLOCKS, +DEQ_BLOCKS): GPTQ int4 -> fp16 W^T [N,K] linear.
// ---------------------------------------------------------------------------
__global__ void __launch_bounds__(256)
k_pre(const float* __restrict__ in, const int* __restrict__ qw,
      const float* __restrict__ sc, const int* __restrict__ qz) {
    if (blockIdx.x < ACONV_BLOCKS) {
        const int l = threadIdx.x & 31;
        int w = (blockIdx.x << 3) | (threadIdx.x >> 5);
        int k16 = w & (K16 - 1);
        int m16 = w >> 8;
        int m = (m16 << 4) + (l >> 2);
        int k = (k16 << 4) + 2 * (l & 3);
        const float* p = in + (size_t)m * KDIM + k;
        float2 f0 = *(const float2*)(p);
        float2 f1 = *(const float2*)(p + 8 * KDIM);
        float2 f2 = *(const float2*)(p + 8);
        float2 f3 = *(const float2*)(p + 8 * KDIM + 8);
        uint4 o;
        o.x = pack_h2(f0.x, f0.y);
        o.y = pack_h2(f1.x, f1.y);
        o.z = pack_h2(f2.x, f2.y);
        o.w = pack_h2(f3.x, f3.y);
        g_Afrag[((size_t)m16 * K16 + k16) * 32 + l] = o;
    } else {
        int idx = (blockIdx.x - ACONV_BLOCKS) * 256 + threadIdx.x;
        int n  = idx & (NDIM - 1);
        int kk = idx >> 12;                         // k/8
        int g  = kk >> 4;                           // group = k/128
        int q  = qw[idx];
        int zw = qz[(g << 9) | (n >> 3)];
        float z = (float)((zw >> ((n & 7) << 2)) & 15);
        float s = sc[(g << 12) | n];
        union { __half2 h[4]; uint4 u; } pk;
#pragma unroll
        for (int j = 0; j < 4; ++j) {
            float w0 = ((float)((q >> (8 * j))     & 15) - z) * s;
            float w1 = ((float)((q >> (8 * j + 4)) & 15) - z) * s;
            pk.h[j] = __floats2half2_rn(w0, w1);
        }
        __half* W = (__half*)g_W16;
        *(uint4*)(W + (size_t)n * KDIM + kk * 8) = pk.u;
    }
}

// ---------------------------------------------------------------------------
// Main GEMM: C = A @ W^T + bias + residual.
// Hybrid: A = direct fragment LDG (register ping-pong, 1 step ahead);
// B = 5-stage cp.async -> swizzled smem -> LDSM pipeline (B-only stages).
// 8 warps (4m x 2n), warp tile 32x64.
// ---------------------------------------------------------------------------
__global__ void __launch_bounds__(256, 2)
k_gemm(const float* __restrict__ residual, const float* __restrict__ bias,
       float* __restrict__ out) {
    extern __shared__ char smem_raw[];
    const uint32_t sbase = smem_u32(smem_raw);

    const int tid  = threadIdx.x;
    const int wid  = tid >> 5;
    const int lane = tid & 31;
    const int warp_m = wid & 3;   // 4 warps along M (32 rows)
    const int warp_n = wid >> 2;  // 2 warps along N (64 cols)

    // L2-friendly raster: supertiles of 8 m-tiles x 32 n-tiles
    const int bid = blockIdx.x;
    const int tm_ = ((bid >> 8) << 3) | (bid & 7);
    const int tn_ = (bid >> 3) & 31;

    // A: fragment pointers (two m16 rows per warp)
    const int m16idx0 = tm_ * 8 + warp_m * 2;
    const uint4* pA0 = g_Afrag + (size_t)m16idx0 * K16 * 32 + lane;
    const uint4* pA1 = pA0 + (size_t)K16 * 32;

    // B: global K-major panel for this n-tile
    const __half* gB = (const __half*)g_W16 + (size_t)tn_ * TN * KDIM;

    // B LDSM per-lane metadata (R8 layout)
    const int tileid = lane >> 3, r8 = lane & 7;
    uint32_t boff[4]; int bsw[4];
    const int bchk = tileid & 1;
#pragma unroll
    for (int nt = 0; nt < 4; ++nt) {
        int br = warp_n * 64 + nt * 16 + ((tileid >> 1) << 3) + r8;
        boff[nt] = (uint32_t)(br << 7);
        bsw[nt] = br & 7;
    }

    // B stage loader geometry: 128 rows x 8 c16; 1024 ops / 256 thr = 4 each
    const int lrow = tid >> 1;          // 0..127
    const int lc16b = (tid & 1) << 2;   // 0 or 4 (each thread does 4 c16)
    const uint32_t lsoff0 = (uint32_t)(lrow << 7);

    auto load_B_full = [&](int c, int slot) {
        const uint32_t sB = sbase + slot * B_TILE_BYTES;
        const __half* pB = gB + (size_t)lrow * KDIM + c * KC + lc16b * 8;
#pragma unroll
        for (int j = 0; j < 4; ++j) {
            int c16 = lc16b + j;
            uint32_t soff = lsoff0 | (uint32_t)((c16 ^ (lrow & 7)) << 4);
            cp_async16(sB + soff, pB + j * 8);
        }
    };

    float acc[2][8][4];
#pragma unroll
    for (int mt = 0; mt < 2; ++mt)
#pragma unroll
        for (int f = 0; f < 8; ++f)
#pragma unroll
            for (int j = 0; j < 4; ++j) acc[mt][f][j] = 0.f;

#define LOAD_BV(bb, sB_, s)                                                    \
    do {                                                                       \
        LDM_X4((bb)[0], (sB_) + boff[0] +                                      \
               (uint32_t)(((((s) << 1) + bchk) ^ bsw[0]) << 4));               \
        LDM_X4((bb)[1], (sB_) + boff[1] +                                      \
               (uint32_t)(((((s) << 1) + bchk) ^ bsw[1]) << 4));               \
        LDM_X4((bb)[2], (sB_) + boff[2] +                                      \
               (uint32_t)(((((s) << 1) + bchk) ^ bsw[2]) << 4));               \
        LDM_X4((bb)[3], (sB_) + boff[3] +                                      \
               (uint32_t)(((((s) << 1) + bchk) ^ bsw[3]) << 4));               \
    } while (0)

#define MMA_MT(mt, Areg, bb)                                                   \
    do {                                                                       \
        const uint32_t* ar = (const uint32_t*)&(Areg);                         \
        _Pragma("unroll")                                                      \
        for (int nt = 0; nt < 4; ++nt) {                                       \
            mma16816(acc[mt][2 * nt],     ar, (bb)[nt]);                       \
            mma16816(acc[mt][2 * nt + 1], ar, (bb)[nt] + 2);                   \
        }                                                                      \
    } while (0)

    // Prologue: B chunks 0..3 in flight (4 groups), then step-0 state
    load_B_full(0, 0);
    asm volatile("cp.async.commit_group;" ::: "memory");
    load_B_full(1, 1);
    asm volatile("cp.async.commit_group;" ::: "memory");
    load_B_full(2, 2);
    asm volatile("cp.async.commit_group;" ::: "memory");
    load_B_full(3, 3);
    asm volatile("cp.async.commit_group;" ::: "memory");
    asm volatile("cp.async.wait_group 3;" ::: "memory");
    __syncthreads();

    uint4 Av0[2], Av1[2];
    uint32_t b0[4][4], b1[4][4];
    LOAD_BV(b0, sbase, 0);          // chunk 0, step 0
    Av0[0] = __ldg(pA0);
    Av0[1] = __ldg(pA1);

#pragma unroll 1
    for (int i = 0; i < NK; ++i) {
        const uint32_t sBc = sbase + (i % NSTAGE_B) * B_TILE_BYTES;

        const int cn = i + 4;
        const bool ld = (cn < NK);
        const int dslot = cn % NSTAGE_B;
        const uint32_t sdst = sbase + dslot * B_TILE_BYTES +
                              lsoff0;
        const __half* pBn = gB + (size_t)lrow * KDIM + cn * KC + lc16b * 8;

        auto cp2 = [&](int j0) {
#pragma unroll
            for (int j = j0; j < j0 + 2; ++j) {
                int c16 = lc16b + j;
                uint32_t soff = (uint32_t)((c16 ^ (lrow & 7)) << 4);
                cp_async16(sdst + soff, pBn + j * 8);
            }
        };

        // ---- step 0 (b0, Av0) ----
        LOAD_BV(b1, sBc, 1);
        Av1[0] = __ldg(pA0 + 32);
        Av1[1] = __ldg(pA1 + 32);
        if (ld) cp2(0);
        MMA_MT(0, Av0[0], b0);
        MMA_MT(1, Av0[1], b0);
        // ---- step 1 (b1, Av1) ----
        LOAD_BV(b0, sBc, 2);
        Av0[0] = __ldg(pA0 + 64);
        Av0[1] = __ldg(pA1 + 64);
        if (ld) cp2(2);
        MMA_MT(0, Av1[0], b1);
        MMA_MT(1, Av1[1], b1);
        asm volatile("cp.async.commit_group;" ::: "memory");
        // ---- step 2 (b0, Av0) ----
        LOAD_BV(b1, sBc, 3);
        Av1[0] = __ldg(pA0 + 96);
        Av1[1] = __ldg(pA1 + 96);
        MMA_MT(0, Av0[0], b0);
        MMA_MT(1, Av0[1], b0);
        // ---- step 3 (b1, Av1) ----
        MMA_MT(0, Av1[0], b1);
        MMA_MT(1, Av1[1], b1);

        pA0 += 128;
        pA1 += 128;

        // barrier: after this, chunk i+1 is resident (3 groups pending)
        asm volatile("cp.async.wait_group 3;" ::: "memory");
        __syncthreads();

        if (i + 1 < NK) {
            const uint32_t sBn = sbase + ((i + 1) % NSTAGE_B) * B_TILE_BYTES;
            LOAD_BV(b0, sBn, 0);
            Av0[0] = __ldg(pA0);
            Av0[1] = __ldg(pA1);
        }
    }

    // Epilogue: fp32 acc + bias + residual -> out
    const int r  = lane >> 2;
    const int c2 = (lane & 3) * 2;
    const int mbase = tm_ * TM + warp_m * 32;
    const int nbase = tn_ * TN + warp_n * 64;
#pragma unroll
    for (int mt = 0; mt < 2; ++mt) {
#pragma unroll
        for (int half = 0; half < 2; ++half) {   // rows r and r+8
            const size_t m = (size_t)(mbase + mt * 16 + r + half * 8);
            const float* rp = residual + m * NDIM + nbase;
            float* op = out + m * NDIM + nbase;
#pragma unroll
            for (int f = 0; f < 8; ++f) {
                const int n = f * 8 + c2;
                float2 res = *(const float2*)(rp + n);
                float2 bz  = *(const float2*)(bias + nbase + n);
                float2 o;
                o.x = acc[mt][f][2 * half]     + bz.x + res.x;
                o.y = acc[mt][f][2 * half + 1] + bz.y + res.y;
                *(float2*)(op + n) = o;
            }
        }
    }
}

// ---------------------------------------------------------------------------
extern "C" void kernel_launch(void* const* d_in, const int* in_sizes, int n_in,
                              void* d_out, int out_size) {
    const float* input    = (const float*)d_in[0];   // [2,4096,4096] f32
    const float* residual = (const float*)d_in[1];   // [2,4096,4096] f32
    const int*   qweight  = (const int*)d_in[2];     // [512,4096] i32
    const float* scales   = (const float*)d_in[3];   // [32,4096] f32
    const int*   qzeros   = (const int*)d_in[4];     // [32,512] i32
    const float* bias     = (const float*)d_in[5];   // [4096] f32
    float* out = (float*)d_out;

    cudaFuncSetAttribute(k_gemm, cudaFuncAttributeMaxDynamicSharedMemorySize,
                         SMEM_DYN);

    k_pre<<<ACONV_BLOCKS + DEQ_BLOCKS, 256>>>(input, qweight, scales, qzeros);

    const int nblocks = (MDIM / TM) * (NDIM / TN);   // 2048
    k_gemm<<<nblocks, 256, SMEM_DYN>>>(residual, bias, out);
}

// round 12
// speedup vs baseline: 1.4395x; 1.4395x over previous
#include <cuda_runtime.h>
#include <cuda_fp16.h>
#include <cstdint>

// Problem dims
#define MDIM 8192   // B*S
#define NDIM 4096
#define KDIM 4096
#define K16  (KDIM / 16)      // 256

// GEMM tiling: 128x128 CTA, 8 warps (4m x 2n), warp tile 32x64
#define TM 128
#define TN 128
#define KC 64                 // k64 chunk = 4 k16 steps
#define NK (KDIM / KC)        // 64
#define NSTAGE 3
#define A_STAGE 16384         // 8 m16-tiles x 4 k16 x 512B
#define B_STAGE 16384         // 2 n64-blocks x 4 k16 x 2048B
#define STAGE_BYTES (A_STAGE + B_STAGE)      // 32768
#define SMEM_DYN (NSTAGE * STAGE_BYTES)      // 98304

// Pre-pass grid split (256-thread blocks, 8 warps each)
#define ACONV_BLOCKS ((MDIM / 16) * K16 / 8)        // 16384
#define DEQ_BLOCKS   ((NDIM / 64) * K16 / 8)        // 2048

// Fragment-layout scratch (allocation-free rule: __device__ globals)
// A: per (m16, k16) tile: 512B block, lane l owns bytes [16l,16l+16) = a0..a3
__device__ uint4 g_Afrag[(MDIM / 16) * (size_t)K16 * 32];
// W: per (n64, k16) block: 2KB; uint4 j*32+l = frags (2j, 2j+1) for lane l
__device__ uint4 g_Wfrag[(NDIM / 64) * (size_t)K16 * 128];

// ---------------------------------------------------------------------------
__device__ __forceinline__ uint32_t smem_u32(const void* p) {
    uint32_t r;
    asm("{ .reg .u64 t; cvta.to.shared.u64 t, %1; cvt.u32.u64 %0, t; }"
        : "=r"(r) : "l"(p));
    return r;
}

__device__ __forceinline__ void cp_async16(uint32_t s, const void* g) {
    asm volatile("cp.async.cg.shared.global [%0], [%1], 16;"
                 :: "r"(s), "l"(__cvta_generic_to_global(g)) : "memory");
}

#define LDS128(v, addr)                                                        \
    asm volatile("ld.shared.v4.b32 {%0,%1,%2,%3}, [%4];"                       \
                 : "=r"((v).x), "=r"((v).y), "=r"((v).z), "=r"((v).w)          \
                 : "r"(addr))

__device__ __forceinline__ void mma16816(float* d, const uint32_t* a,
                                         const uint32_t* b) {
    asm volatile(
        "mma.sync.aligned.m16n8k16.row.col.f32.f16.f16.f32 "
        "{%0,%1,%2,%3}, {%4,%5,%6,%7}, {%8,%9}, {%0,%1,%2,%3};"
        : "+f"(d[0]), "+f"(d[1]), "+f"(d[2]), "+f"(d[3])
        : "r"(a[0]), "r"(a[1]), "r"(a[2]), "r"(a[3]), "r"(b[0]), "r"(b[1]));
}

__device__ __forceinline__ uint32_t pack_h2(float x, float y) {
    __half2 h = __floats2half2_rn(x, y);
    return *(uint32_t*)&h;
}

// ---------------------------------------------------------------------------
// Merged pre-pass (R10's, proven numerics + throughput).
// Blocks [0, ACONV_BLOCKS): A fp32 -> fp16 fragments, warp per (m16,k16).
// Blocks [ACONV_BLOCKS, ...): GPTQ int4 dequant -> B fragments, warp per
// (n64, k16).
// ---------------------------------------------------------------------------
__global__ void __launch_bounds__(256)
k_pre(const float* __restrict__ in, const int* __restrict__ qw,
      const float* __restrict__ sc, const int* __restrict__ qz) {
    const int l = threadIdx.x & 31;
    if (blockIdx.x < ACONV_BLOCKS) {
        int w = (blockIdx.x << 3) | (threadIdx.x >> 5);
        int k16 = w & (K16 - 1);
        int m16 = w >> 8;
        int m = (m16 << 4) + (l >> 2);
        int k = (k16 << 4) + 2 * (l & 3);
        const float* p = in + (size_t)m * KDIM + k;
        float2 f0 = *(const float2*)(p);
        float2 f1 = *(const float2*)(p + 8 * KDIM);
        float2 f2 = *(const float2*)(p + 8);
        float2 f3 = *(const float2*)(p + 8 * KDIM + 8);
        uint4 o;
        o.x = pack_h2(f0.x, f0.y);
        o.y = pack_h2(f1.x, f1.y);
        o.z = pack_h2(f2.x, f2.y);
        o.w = pack_h2(f3.x, f3.y);
        g_Afrag[((size_t)m16 * K16 + k16) * 32 + l] = o;
    } else {
        int w = ((blockIdx.x - ACONV_BLOCKS) << 3) | (threadIdx.x >> 5);
        int k16 = w & (K16 - 1);
        int n64 = w >> 8;                 // 0..63
        int nb = n64 << 6;
        int g   = k16 >> 3;               // group = k/128
        int kk0 = k16 << 1;               // q row for k 0..7 of this tile
        int sh  = (l & 3) << 3;           // nibble-pair start bit
        uint4 ov[4];
#pragma unroll
        for (int j = 0; j < 4; ++j) {
            uint32_t r[4];
#pragma unroll
            for (int h = 0; h < 2; ++h) {
                int f = 2 * j + h;
                int n = nb + f * 8 + (l >> 2);
                uint32_t q0 = (uint32_t)qw[(size_t)kk0 * NDIM + n];
                uint32_t q1 = (uint32_t)qw[(size_t)(kk0 + 1) * NDIM + n];
                float s = sc[(size_t)g * NDIM + n];
                int zw = qz[g * (NDIM / 8) + (n >> 3)];
                float z = (float)((zw >> ((n & 7) << 2)) & 15);
                float w00 = ((float)((q0 >> sh) & 15) - z) * s;
                float w01 = ((float)((q0 >> (sh + 4)) & 15) - z) * s;
                float w10 = ((float)((q1 >> sh) & 15) - z) * s;
                float w11 = ((float)((q1 >> (sh + 4)) & 15) - z) * s;
                r[2 * h]     = pack_h2(w00, w01);   // reg0 (k 0-7)
                r[2 * h + 1] = pack_h2(w10, w11);   // reg1 (k 8-15)
            }
            ov[j].x = r[0]; ov[j].y = r[1]; ov[j].z = r[2]; ov[j].w = r[3];
        }
        uint4* dst = g_Wfrag + ((size_t)n64 * K16 + k16) * 128 + l;
#pragma unroll
        for (int j = 0; j < 4; ++j) dst[j * 32] = ov[j];
    }
}

// ---------------------------------------------------------------------------
// Main GEMM: C = A @ W^T + bias + residual.
// R8's pipeline schedule over fragment-layout operands: cp.async linear
// block copies -> smem -> ld.shared.v4 fragment reads (no swizzle, no LDSM
// metadata). B ping-pong + mid-step A reloads; cp.async pairs interleaved
// between MMA groups; barrier at iter end + next-stage preload; slot ring
// via pointer rotation.
// ---------------------------------------------------------------------------
__global__ void __launch_bounds__(256, 2)
k_gemm(const float* __restrict__ residual, const float* __restrict__ bias,
       float* __restrict__ out) {
    extern __shared__ char smem_raw[];
    const uint32_t sbase = smem_u32(smem_raw);

    const int tid  = threadIdx.x;
    const int wid  = tid >> 5;
    const int lane = tid & 31;
    const int warp_m = wid & 3;   // 4 warps along M (32 rows)
    const int warp_n = wid >> 2;  // 2 warps along N (64 cols)

    // L2-friendly raster: supertiles of 8 m-tiles x 32 n-tiles
    const int bid = blockIdx.x;
    const int tm_ = ((bid >> 8) << 3) | (bid & 7);
    const int tn_ = (bid >> 3) & 31;

    // Global fragment panels for this CTA
    const uint4* gA = g_Afrag + (size_t)(tm_ * 8) * K16 * 32;
    const uint4* gW = g_Wfrag + (size_t)(tn_ * 2) * K16 * 128;

    // Loader per-thread geometry.
    // A: rep r in 0..3 copies 16B of m16-tile (ab + 2r), chunk-contiguous 2KB.
    const int ab = tid >> 7;            // 0/1
    const int ainner = tid & 127;
    const uint4* pAc = gA + (size_t)ab * (K16 * 32) + ainner;   // +c*128/chunk
    const uint4* pBc = gW + tid;                                 // +c*512/chunk
    const uint32_t adst = (uint32_t)(ab * 2048 + ainner * 16);
    const uint32_t bdst = (uint32_t)(A_STAGE + tid * 16);

    // Compute-side smem read bases (add stage base; + mt*2048 + s*512 for A,
    // + s*2048 + j*512 for B)
    const uint32_t aRd = (uint32_t)((warp_m * 2) * 2048 + lane * 16);
    const uint32_t bRd = (uint32_t)(A_STAGE + warp_n * 8192 + lane * 16);

    float acc[2][8][4];
#pragma unroll
    for (int mt = 0; mt < 2; ++mt)
#pragma unroll
        for (int f = 0; f < 8; ++f)
#pragma unroll
            for (int j = 0; j < 4; ++j) acc[mt][f][j] = 0.f;

#define LOAD_BV(bb, sB_, s)                                                    \
    do {                                                                       \
        LDS128((bb)[0], (sB_) + (s) * 2048);                                   \
        LDS128((bb)[1], (sB_) + (s) * 2048 + 512);                             \
        LDS128((bb)[2], (sB_) + (s) * 2048 + 1024);                            \
        LDS128((bb)[3], (sB_) + (s) * 2048 + 1536);                            \
    } while (0)

#define MMA_MT(mt, Areg, bb)                                                   \
    do {                                                                       \
        const uint32_t* ar = (const uint32_t*)&(Areg);                         \
        _Pragma("unroll")                                                      \
        for (int nt = 0; nt < 4; ++nt) {                                       \
            const uint32_t* br = (const uint32_t*)&(bb)[nt];                   \
            mma16816(acc[mt][2 * nt],     ar, br);                             \
            mma16816(acc[mt][2 * nt + 1], ar, br + 2);                         \
        }                                                                      \
    } while (0)

    // Full-stage load (prologue)
    auto load_full = [&](int c, uint32_t sdst) {
#pragma unroll
        for (int r = 0; r < 4; ++r)
            cp_async16(sdst + adst + r * 4096, pAc + (size_t)c * 128 + r * 16384);
#pragma unroll
        for (int r = 0; r < 4; ++r)
            cp_async16(sdst + bdst + (r >> 1) * 8192 + (r & 1) * 4096,
                       pBc + (size_t)c * 512 + (r >> 1) * 32768 + (r & 1) * 256);
    };

    load_full(0, sbase);
    asm volatile("cp.async.commit_group;" ::: "memory");
    load_full(1, sbase + STAGE_BYTES);
    asm volatile("cp.async.commit_group;" ::: "memory");
    asm volatile("cp.async.wait_group 1;" ::: "memory");
    __syncthreads();

    // Slot ring pointers: cur = slot(i), nxt = slot(i+1), dst = slot(i+2)
    uint32_t sCur = sbase;
    uint32_t sNxt = sbase + STAGE_BYTES;
    uint32_t sDst = sbase + 2 * STAGE_BYTES;

    // Advance loader pointers to chunk 2
    pAc += 2 * 128;
    pBc += 2 * 512;

    uint4 A0, A1, Bv0[4], Bv1[4];
    LOAD_BV(Bv0, sCur + bRd, 0);
    LDS128(A0, sCur + aRd);
    LDS128(A1, sCur + aRd + 2048);

#pragma unroll 1
    for (int i = 0; i < NK; ++i) {
        const uint32_t sAc = sCur + aRd;
        const uint32_t sBc = sCur + bRd;
        const bool ld = (i + 2 < NK);

        // ---- step 0 (Bv0, A0/A1) ----
        LOAD_BV(Bv1, sBc, 1);
        if (ld) {
            cp_async16(sDst + adst, pAc);
            cp_async16(sDst + adst + 4096, pAc + 16384);
        }
        MMA_MT(0, A0, Bv0);
        LDS128(A0, sAc + 512);
        if (ld) {
            cp_async16(sDst + adst + 8192, pAc + 32768);
            cp_async16(sDst + adst + 12288, pAc + 49152);
        }
        MMA_MT(1, A1, Bv0);
        LDS128(A1, sAc + 2048 + 512);

        // ---- step 1 (Bv1) ----
        LOAD_BV(Bv0, sBc, 2);
        if (ld) {
            cp_async16(sDst + bdst, pBc);
            cp_async16(sDst + bdst + 4096, pBc + 256);
        }
        MMA_MT(0, A0, Bv1);
        LDS128(A0, sAc + 1024);
        if (ld) {
            cp_async16(sDst + bdst + 8192, pBc + 32768);
            cp_async16(sDst + bdst + 12288, pBc + 33024);
        }
        MMA_MT(1, A1, Bv1);
        LDS128(A1, sAc + 2048 + 1024);
        asm volatile("cp.async.commit_group;" ::: "memory");

        // ---- step 2 (Bv0) ----
        LOAD_BV(Bv1, sBc, 3);
        MMA_MT(0, A0, Bv0);
        LDS128(A0, sAc + 1536);
        MMA_MT(1, A1, Bv0);
        LDS128(A1, sAc + 2048 + 1536);

        // ---- step 3 (Bv1) ----
        MMA_MT(0, A0, Bv1);
        MMA_MT(1, A1, Bv1);

        pAc += 128;
        pBc += 512;

        // barrier: afterwards chunk i+1 resident (1 group pending)
        asm volatile("cp.async.wait_group 1;" ::: "memory");
        __syncthreads();

        // preload step-0 fragments of chunk i+1 so next iter opens with MMAs
        if (i + 1 < NK) {
            LOAD_BV(Bv0, sNxt + bRd, 0);
            LDS128(A0, sNxt + aRd);
            LDS128(A1, sNxt + aRd + 2048);
        }

        // rotate slot ring
        uint32_t t = sCur;
        sCur = sNxt;
        sNxt = sDst;
        sDst = t;
    }

    // Epilogue: fp32 acc + bias + residual -> out
    const int r  = lane >> 2;
    const int c2 = (lane & 3) * 2;
    const int mbase = tm_ * TM + warp_m * 32;
    const int nbase = tn_ * TN + warp_n * 64;
#pragma unroll
    for (int mt = 0; mt < 2; ++mt) {
#pragma unroll
        for (int half = 0; half < 2; ++half) {   // rows r and r+8
            const size_t m = (size_t)(mbase + mt * 16 + r + half * 8);
            const float* rp = residual + m * NDIM + nbase;
            float* op = out + m * NDIM + nbase;
#pragma unroll
            for (int f = 0; f < 8; ++f) {
                const int n = f * 8 + c2;
                float2 res = *(const float2*)(rp + n);
                float2 bz  = *(const float2*)(bias + nbase + n);
                float2 o;
                o.x = acc[mt][f][2 * half]     + bz.x + res.x;
                o.y = acc[mt][f][2 * half + 1] + bz.y + res.y;
                *(float2*)(op + n) = o;
            }
        }
    }
}

// ---------------------------------------------------------------------------
extern "C" void kernel_launch(void* const* d_in, const int* in_sizes, int n_in,
                              void* d_out, int out_size) {
    const float* input    = (const float*)d_in[0];   // [2,4096,4096] f32
    const float* residual = (const float*)d_in[1];   // [2,4096,4096] f32
    const int*   qweight  = (const int*)d_in[2];     // [512,4096] i32
    const float* scales   = (const float*)d_in[3];   // [32,4096] f32
    const int*   qzeros   = (const int*)d_in[4];     // [32,512] i32
    const float* bias     = (const float*)d_in[5];   // [4096] f32
    float* out = (float*)d_out;

    cudaFuncSetAttribute(k_gemm, cudaFuncAttributeMaxDynamicSharedMemorySize,
                         SMEM_DYN);

    k_pre<<<ACONV_BLOCKS + DEQ_BLOCKS, 256>>>(input, qweight, scales, qzeros);

    const int nblocks = (MDIM / TM) * (NDIM / TN);   // 2048
    k_gemm<<<nblocks, 256, SMEM_DYN>>>(residual, bias, out);
}